// round 15
// baseline (speedup 1.0000x reference)
#include <cuda_runtime.h>
#include <cuda_bf16.h>
#include <stdint.h>
#include <math.h>

typedef uint32_t u32;
typedef uint64_t u64;

static constexpr int THREADS = 512;     // 16 warps: (m-tile 0-7) x (n-half 0-1)
static constexpr int MT      = 128;     // points per CTA
static constexpr float OMEGA = 30.0f;
static constexpr int NSUB    = 52;      // 26 units x (hi,lo) 32KB subunits
static constexpr int SUB_BYTES = 32768;

// ---- shared memory layout (bytes) ----
static constexpr int RING_OFF = 0;            // 3 x 32KB weight ring
static constexpr int XB_OFF   = 98304;        // x frags: 8 m-tiles x 8KB
static constexpr int HB_OFF   = 163840;       // h / ff frags: 8 m-tiles x 8KB (also output stage)
static constexpr int BOW_OFF  = 229376;       // B (256 f) + out_w (128 f)
static constexpr int MBAR_OFF = 230912;       // full[3] + cnt[3]
static constexpr int SMEM_BYTES = 231424;

// weight blob: 52 subunits x 32KB, execution order, bf16 [n][k] swizzled
__device__ __align__(16) unsigned char g_wblob[(size_t)NSUB * SUB_BYTES];
// precombined bias for epilogue2: b2[l] (+ skb[l/2] on even l)
__device__ __align__(16) float g_b2c[8 * 128];

// ============================ PTX helpers ============================

__device__ __forceinline__ u32 smem_u32(const void* p) {
    return (u32)__cvta_generic_to_shared(p);
}

#define MBARRIER_INIT(addr, cnt) \
    asm volatile("mbarrier.init.shared.b64 [%0], %1;" :: "r"(addr), "r"((u32)(cnt)) : "memory")
#define MBARRIER_EXPECT_TX(addr, b) \
    asm volatile("mbarrier.arrive.expect_tx.shared.b64 _, [%0], %1;" :: "r"(addr), "r"((u32)(b)) : "memory")

#define MBARRIER_WAIT_PARITY(mbar_smem_addr, phase_parity) do { \
    u32 _mbar = (u32)(mbar_smem_addr); \
    u32 _parity = (u32)(phase_parity); \
    u32 _done; \
    asm volatile( \
        "{\n\t.reg .pred p;\n\t" \
        "mbarrier.try_wait.parity.acquire.cta.shared::cta.b64 p, [%1], %2;\n\t" \
        "selp.b32 %0, 1, 0, p;\n\t}" \
        : "=r"(_done) : "r"(_mbar), "r"(_parity) : "memory"); \
    if (!_done) { \
        asm volatile( \
            "{\n\t.reg .pred P1;\n\t" \
            "WAIT_LOOP_%=:\n\t" \
            "mbarrier.try_wait.parity.acquire.cta.shared::cta.b64 P1, [%0], %1, 0x989680;\n\t" \
            "@P1 bra.uni WAIT_DONE_%=;\n\t" \
            "bra.uni WAIT_LOOP_%=;\n\t" \
            "WAIT_DONE_%=:\n\t}" \
            :: "r"(_mbar), "r"(_parity) : "memory"); \
    } \
} while (0)

__device__ __forceinline__ void bulk_copy(u32 dst, const void* src, u32 bytes, u32 mbar) {
    asm volatile(
        "cp.async.bulk.shared::cluster.global.mbarrier::complete_tx::bytes [%0], [%1], %2, [%3];"
        :: "r"(dst), "l"(src), "r"(bytes), "r"(mbar) : "memory");
}

__device__ __forceinline__ void ldsm4(u32& r0, u32& r1, u32& r2, u32& r3, u32 addr) {
    asm volatile("ldmatrix.sync.aligned.m8n8.x4.shared.b16 {%0,%1,%2,%3}, [%4];"
                 : "=r"(r0), "=r"(r1), "=r"(r2), "=r"(r3) : "r"(addr));
}

__device__ __forceinline__ void mma16816(float (&d)[4], const u32 (&a)[4], u32 b0, u32 b1) {
    asm volatile(
        "mma.sync.aligned.m16n8k16.row.col.f32.bf16.bf16.f32 "
        "{%0,%1,%2,%3},{%4,%5,%6,%7},{%8,%9},{%0,%1,%2,%3};"
        : "+f"(d[0]), "+f"(d[1]), "+f"(d[2]), "+f"(d[3])
        : "r"(a[0]), "r"(a[1]), "r"(a[2]), "r"(a[3]), "r"(b0), "r"(b1));
}

// bf16 -> f32 is exactly bits<<16 (cheap ALU, no CVT)
__device__ __forceinline__ float bflo(u32 v) { return __uint_as_float(v << 16); }
__device__ __forceinline__ float bfhi(u32 v) { return __uint_as_float(v & 0xFFFF0000u); }

// split v0,v1 into packed bf16 hi + packed bf16 lo (residual)
__device__ __forceinline__ void bf_split2(float v0, float v1, u32& hi, u32& lo) {
    asm("cvt.rn.bf16x2.f32 %0, %1, %2;" : "=r"(hi) : "f"(v1), "f"(v0));
    float r0 = v0 - bflo(hi);
    float r1 = v1 - bfhi(hi);
    asm("cvt.rn.bf16x2.f32 %0, %1, %2;" : "=r"(lo) : "f"(r1), "f"(r0));
}

// ---- fast transcendentals (err ~1e-6, far below bf16-split noise) ----
__device__ __forceinline__ float fast_sin(float x) {
    float k = rintf(x * 0.15915494309189535f);
    float r = fmaf(k, -6.28125f, x);
    r = fmaf(k, -1.9353071795864769e-3f, r);
    float s;
    asm("sin.approx.f32 %0, %1;" : "=f"(s) : "f"(r));
    return s;
}
__device__ __forceinline__ float fast_cos(float x) {
    float k = rintf(x * 0.15915494309189535f);
    float r = fmaf(k, -6.28125f, x);
    r = fmaf(k, -1.9353071795864769e-3f, r);
    float c;
    asm("cos.approx.f32 %0, %1;" : "=f"(c) : "f"(r));
    return c;
}
__device__ __forceinline__ float fast_tanh(float x) {
    float e;
    asm("ex2.approx.f32 %0, %1;" : "=f"(e) : "f"(x * 2.8853900817779268f));
    float r;
    asm("rcp.approx.f32 %0, %1;" : "=f"(r) : "f"(e + 1.0f));
    return fmaf(-2.0f, r, 1.0f);
}

// ==================== weight conversion pre-kernel (unchanged) ====================
__global__ void convert_weights(const float* __restrict__ in_w,
                                const float* __restrict__ w1,
                                const float* __restrict__ w2,
                                const float* __restrict__ skw,
                                const float* __restrict__ b2,
                                const float* __restrict__ skb) {
    int gid = blockIdx.x * blockDim.x + threadIdx.x;
    if (gid >= 26 * 16384) return;

    if (gid < 8 * 128) {
        int l = gid >> 7, c = gid & 127;
        float v = b2[l * 128 + c];
        if ((l & 1) == 0) v += skb[(l >> 1) * 128 + c];
        g_b2c[gid] = v;
    }

    int u = gid >> 14, e = gid & 16383;
    int n = e >> 7, k = e & 127;

    float v;
    if (u < 2) {
        v = in_w[(k + u * 128) * 128 + n];
    } else {
        int r = u - 2, l = 0;
        while (true) {
            int len = ((l & 1) == 0) ? 4 : 2;
            if (r < len) break;
            r -= len; l++;
        }
        if (r == 0)      v = w1[l * 16384 + k * 128 + n];
        else if (r == 1) v = w2[l * 16384 + k * 128 + n];
        else             v = skw[(l >> 1) * 32768 + (k + (r - 2) * 128) * 128 + n];
    }

    __nv_bfloat16 hi = __float2bfloat16_rn(v);
    float rem = v - __bfloat162float(hi);
    __nv_bfloat16 lo = __float2bfloat16_rn(rem);

    u32 off = (u32)(n * 256 + ((2 * k) ^ ((n & 7) << 4)));
    size_t base = (size_t)u * 65536;
    *(__nv_bfloat16*)(g_wblob + base + off)         = hi;
    *(__nv_bfloat16*)(g_wblob + base + 32768 + off) = lo;
}

// ==================== GEMM: A from smem frag records ====================
// Warp tile: m16 x n64 (local ntp 0..3, global ntp = nhalf*4 + i).
// fr points at this m-tile's record base + lane*16; records (kstep*2+rp)*512:
//   rec0 int4 = {ah(nt even,row g), ah(nt odd,row g), al(even,g), al(odd,g)}
//   rec1 same for row g+8.
__device__ __forceinline__ void gemm_smem(u32 wbase, const char* fr, bool isHi,
                                          float (&d)[8][4], int lane, int nhalf) {
    const u32 off0 = (u32)((((lane & 7) + ((lane >> 4) << 3))) * 256);
    const u32 swz  = (u32)((lane & 7) << 4);
    const u32 kh   = (u32)(((lane >> 3) & 1) * 16);
#pragma unroll
    for (int s = 0; s < 8; s++) {
        const int4 q0 = *(const int4*)(fr + (s * 2 + 0) * 512);
        const int4 q1 = *(const int4*)(fr + (s * 2 + 1) * 512);
        u32 ah[4] = {(u32)q0.x, (u32)q1.x, (u32)q0.y, (u32)q1.y};
        u32 al[4] = {(u32)q0.z, (u32)q1.z, (u32)q0.w, (u32)q1.w};
#pragma unroll
        for (int i = 0; i < 4; i++) {
            int ntp_g = nhalf * 4 + i;
            u32 r0, r1, r2, r3;
            ldsm4(r0, r1, r2, r3, wbase + off0 + (u32)(ntp_g * 4096) + (((u32)(32 * s) + kh) ^ swz));
            mma16816(d[2 * i],     ah, r0, r1);
            mma16816(d[2 * i + 1], ah, r2, r3);
            if (isHi) {
                mma16816(d[2 * i],     al, r0, r1);
                mma16816(d[2 * i + 1], al, r2, r3);
            }
        }
    }
}

// ff frag writer: this warp fills ksteps nhalf*4..+3 of one trig half.
__device__ __forceinline__ void write_ff(bool useCos, const float* __restrict__ Bs,
                                         float s0, float t0, float s1, float t1,
                                         int qc, int nhalf, char* dst) {
#pragma unroll
    for (int tl = 0; tl < 4; tl++) {
        int t = nhalf * 4 + tl;
        int f0 = 16 * t + 2 * qc;
        float v0[4], v1[4];
#pragma unroll
        for (int j = 0; j < 4; j++) {
            int f = f0 + ((j & 1) ? 1 : 0) + ((j & 2) ? 8 : 0);
            float p0 = s0 * Bs[f] + t0 * Bs[128 + f];
            float p1 = s1 * Bs[f] + t1 * Bs[128 + f];
            v0[j] = useCos ? fast_cos(p0) : fast_sin(p0);
            v1[j] = useCos ? fast_cos(p1) : fast_sin(p1);
        }
        u32 h0, l0, h1, l1, h2, l2, h3, l3;
        bf_split2(v0[0], v0[1], h0, l0);
        bf_split2(v1[0], v1[1], h1, l1);
        bf_split2(v0[2], v0[3], h2, l2);
        bf_split2(v1[2], v1[3], h3, l3);
        *(int4*)(dst + (t * 2 + 0) * 512) = make_int4((int)h0, (int)h2, (int)l0, (int)l2);
        *(int4*)(dst + (t * 2 + 1) * 512) = make_int4((int)h1, (int)h3, (int)l1, (int)l3);
    }
}

// epilogue writer, EMODE: 0 = input sin, 1 = tanh -> h, 2 = residual x update
template<int EMODE>
__device__ __forceinline__ void epi_store(float (&d)[8][4], const float* __restrict__ bias,
                                          char* dst, int qc, int nhalf) {
#pragma unroll
    for (int tl = 0; tl < 4; tl++) {
        int nt0 = 2 * tl, nt1 = 2 * tl + 1;
        int c0 = 8 * (nhalf * 8 + nt0) + 2 * qc;
        float2 b0 = *(const float2*)(bias + c0);
        float2 b1v = *(const float2*)(bias + c0 + 8);
        float v[2][4];
        v[0][0] = d[nt0][0] + b0.x;  v[0][1] = d[nt0][1] + b0.y;
        v[1][0] = d[nt0][2] + b0.x;  v[1][1] = d[nt0][3] + b0.y;
        v[0][2] = d[nt1][0] + b1v.x; v[0][3] = d[nt1][1] + b1v.y;
        v[1][2] = d[nt1][2] + b1v.x; v[1][3] = d[nt1][3] + b1v.y;
        if (EMODE == 2) {
            int4 o0 = *(int4*)(dst + ((nhalf * 4 + tl) * 2 + 0) * 512);
            int4 o1 = *(int4*)(dst + ((nhalf * 4 + tl) * 2 + 1) * 512);
            v[0][0] += bflo((u32)o0.x) + bflo((u32)o0.z);
            v[0][1] += bfhi((u32)o0.x) + bfhi((u32)o0.z);
            v[0][2] += bflo((u32)o0.y) + bflo((u32)o0.w);
            v[0][3] += bfhi((u32)o0.y) + bfhi((u32)o0.w);
            v[1][0] += bflo((u32)o1.x) + bflo((u32)o1.z);
            v[1][1] += bfhi((u32)o1.x) + bfhi((u32)o1.z);
            v[1][2] += bflo((u32)o1.y) + bflo((u32)o1.w);
            v[1][3] += bfhi((u32)o1.y) + bfhi((u32)o1.w);
        } else if (EMODE == 0) {
#pragma unroll
            for (int r = 0; r < 2; r++)
#pragma unroll
                for (int j = 0; j < 4; j++) v[r][j] = fast_sin(OMEGA * v[r][j]);
        } else {
#pragma unroll
            for (int r = 0; r < 2; r++)
#pragma unroll
                for (int j = 0; j < 4; j++) v[r][j] = fast_tanh(v[r][j]);
        }
        u32 h0, l0, h1, l1, h2, l2, h3, l3;
        bf_split2(v[0][0], v[0][1], h0, l0);
        bf_split2(v[1][0], v[1][1], h1, l1);
        bf_split2(v[0][2], v[0][3], h2, l2);
        bf_split2(v[1][2], v[1][3], h3, l3);
        *(int4*)(dst + ((nhalf * 4 + tl) * 2 + 0) * 512) = make_int4((int)h0, (int)h2, (int)l0, (int)l2);
        *(int4*)(dst + ((nhalf * 4 + tl) * 2 + 1) * 512) = make_int4((int)h1, (int)h3, (int)l1, (int)l3);
    }
}

__device__ __forceinline__ void zero_d(float (&d)[8][4]) {
#pragma unroll
    for (int i = 0; i < 8; i++)
#pragma unroll
        for (int j = 0; j < 4; j++) d[i][j] = 0.0f;
}

__device__ __forceinline__ void prefetch_sub(u32 ring, u32 mbf, int sub) {
    u32 mb = mbf + 8 * (sub % 3);
    MBARRIER_EXPECT_TX(mb, SUB_BYTES);
    bulk_copy(ring + (sub % 3) * SUB_BYTES, g_wblob + (size_t)sub * SUB_BYTES, SUB_BYTES, mb);
}

// ==================== main kernel ====================

extern __shared__ __align__(16) char smem[];

__global__ void __launch_bounds__(THREADS, 1)
pinn_mma(const float* __restrict__ S,  const float* __restrict__ Tt,
         const float* __restrict__ Bm,
         const float* __restrict__ in_b, const float* __restrict__ b1,
         const float* __restrict__ ow,   const float* __restrict__ ob,
         float* __restrict__ out, int N)
{
    const int tid   = threadIdx.x;
    const int warp  = tid >> 5, lane = tid & 31;
    const int mt    = warp & 7;        // m-tile 0..7
    const int nhalf = warp >> 3;       // n-half 0..1
    const int grp   = lane >> 2, qc = lane & 3;
    const int base  = blockIdx.x * MT;
    const int barid = mt + 1;          // named barrier per pair (1..8)

    const u32 sb   = smem_u32(smem);
    const u32 ring = sb + RING_OFF;
    const u32 mbf  = sb + MBAR_OFF;
    u32* cnt = (u32*)(smem + MBAR_OFF + 24);
    float* Bs  = (float*)(smem + BOW_OFF);     // 256 floats
    float* ows = Bs + 256;                     // 128 floats
    char* fr_x = smem + XB_OFF + mt * 8192 + lane * 16;
    char* fr_h = smem + HB_OFF + mt * 8192 + lane * 16;

#define PB() asm volatile("bar.sync %0, 64;" :: "r"(barid) : "memory")

    if (tid == 0) {
        MBARRIER_INIT(mbf + 0,  1);
        MBARRIER_INIT(mbf + 8,  1);
        MBARRIER_INIT(mbf + 16, 1);
        cnt[0] = 0; cnt[1] = 0; cnt[2] = 0;
    }
    __syncthreads();

    if (tid == 0) {
        prefetch_sub(ring, mbf, 0);
        prefetch_sub(ring, mbf, 1);
        prefetch_sub(ring, mbf, 2);
    }

    if (tid < 256) Bs[tid] = Bm[tid];
    if (tid < 128) ows[tid] = ow[tid];

    // this warp's two point rows (same for both warps of a pair)
    const int r0g = base + mt * 16 + grp;
    const int r1g = r0g + 8;
    const float s0 = (r0g < N) ? S[r0g]  : 0.0f;
    const float t0 = (r0g < N) ? Tt[r0g] : 0.0f;
    const float s1 = (r1g < N) ? S[r1g]  : 0.0f;
    const float t1 = (r1g < N) ? Tt[r1g] : 0.0f;
    __syncthreads();

    // pair-level phase stagger: pairs mt 4-7 delayed ~half epilogue so each
    // SMSP's two pairs run anti-phase (SMSP s hosts pairs s and s+4)
    if (mt & 4) {
        u32 c0; asm volatile("mov.u32 %0, %%clock;" : "=r"(c0));
        u32 el = 0;
        do { u32 c; asm volatile("mov.u32 %0, %%clock;" : "=r"(c)); el = c - c0; } while (el < 1300u);
    }

    int sub = 0;
    float d[8][4];

#define DO_SUB(isHi, FR) do { \
        MBARRIER_WAIT_PARITY(mbf + 8 * (sub % 3), (sub / 3) & 1); \
        gemm_smem(ring + (u32)((sub % 3) * SUB_BYTES), (FR), (isHi), d, lane, nhalf); \
        if (lane == 0) { \
            u32 old = atomicAdd(&cnt[sub % 3], 1u); \
            if (old == 16u * (u32)(sub / 3) + 15u && sub + 3 < NSUB) \
                prefetch_sub(ring, mbf, sub + 3); \
        } \
        sub++; \
    } while (0)

    // ---- input layer: D = ff @ in_w (K=256 as sin half + cos half) ----
    zero_d(d);
    write_ff(false, Bs, s0, t0, s1, t1, qc, nhalf, fr_h);
    PB();
    DO_SUB(true, fr_h);  DO_SUB(false, fr_h);
    PB();
    write_ff(true, Bs, s0, t0, s1, t1, qc, nhalf, fr_h);
    PB();
    DO_SUB(true, fr_h);  DO_SUB(false, fr_h);
    epi_store<0>(d, in_b, fr_x, qc, nhalf);   // x = sin(OMEGA*(D+in_b)) -> xbuf

    // ---- residual blocks ----
    for (int l = 0; l < 8; l++) {
        const bool skip = ((l & 1) == 0);

        // GEMM1: D = x @ w1_l ; h = tanh(D + b1_l) -> hbuf
        PB();                        // both halves of x written; prev hbuf reads done
        zero_d(d);
        DO_SUB(true, fr_x);  DO_SUB(false, fr_x);
        epi_store<1>(d, b1 + l * 128, fr_h, qc, nhalf);
        PB();                        // h complete before GEMM2 reads

        // GEMM2: D = h @ w2_l (+ ff @ skip_w[l/2])
        zero_d(d);
        DO_SUB(true, fr_h);  DO_SUB(false, fr_h);
        if (skip) {
            PB();                    // pair done reading h; reuse hbuf for ff
            write_ff(false, Bs, s0, t0, s1, t1, qc, nhalf, fr_h);
            PB();
            DO_SUB(true, fr_h);  DO_SUB(false, fr_h);
            PB();
            write_ff(true, Bs, s0, t0, s1, t1, qc, nhalf, fr_h);
            PB();
            DO_SUB(true, fr_h);  DO_SUB(false, fr_h);
        }
        // epilogue2: x += D + b2c (reads/writes OWN xbuf slots only)
        epi_store<2>(d, g_b2c + l * 128, fr_x, qc, nhalf);
    }

    // ---- output layer: out = x @ out_w + out_b ----
    float a0 = 0.0f, a1 = 0.0f;
#pragma unroll
    for (int tl = 0; tl < 4; tl++) {
        int4 o0 = *(int4*)(fr_x + ((nhalf * 4 + tl) * 2 + 0) * 512);
        int4 o1 = *(int4*)(fr_x + ((nhalf * 4 + tl) * 2 + 1) * 512);
        int c0 = 8 * (nhalf * 8 + 2 * tl) + 2 * qc;
        float w00 = ows[c0],     w01 = ows[c0 + 1];
        float w10 = ows[c0 + 8], w11 = ows[c0 + 9];
        a0 += (bflo((u32)o0.x) + bflo((u32)o0.z)) * w00
            + (bfhi((u32)o0.x) + bfhi((u32)o0.z)) * w01
            + (bflo((u32)o0.y) + bflo((u32)o0.w)) * w10
            + (bfhi((u32)o0.y) + bfhi((u32)o0.w)) * w11;
        a1 += (bflo((u32)o1.x) + bflo((u32)o1.z)) * w00
            + (bfhi((u32)o1.x) + bfhi((u32)o1.z)) * w01
            + (bflo((u32)o1.y) + bflo((u32)o1.w)) * w10
            + (bfhi((u32)o1.y) + bfhi((u32)o1.w)) * w11;
    }
    a0 += __shfl_xor_sync(0xFFFFFFFF, a0, 1);
    a0 += __shfl_xor_sync(0xFFFFFFFF, a0, 2);
    a1 += __shfl_xor_sync(0xFFFFFFFF, a1, 1);
    a1 += __shfl_xor_sync(0xFFFFFFFF, a1, 2);

    float* stage = (float*)(smem + HB_OFF);   // reuse hbuf as [128 rows][2 halves]
    __syncthreads();
    if (qc == 0) {
        stage[(mt * 16 + grp) * 2 + nhalf]     = a0;
        stage[(mt * 16 + grp + 8) * 2 + nhalf] = a1;
    }
    __syncthreads();
    if (tid < 128) {
        int g = base + tid;
        if (g < N) out[g] = stage[2 * tid] + stage[2 * tid + 1] + ob[0];
    }
#undef DO_SUB
#undef PB
}

// ==================== launcher ====================

extern "C" void kernel_launch(void* const* d_in, const int* in_sizes, int n_in,
                              void* d_out, int out_size) {
    const float* S    = (const float*)d_in[0];
    const float* T    = (const float*)d_in[1];
    const float* B    = (const float*)d_in[2];
    const float* in_w = (const float*)d_in[3];
    const float* in_b = (const float*)d_in[4];
    const float* w1   = (const float*)d_in[5];
    const float* b1   = (const float*)d_in[6];
    const float* w2   = (const float*)d_in[7];
    const float* b2   = (const float*)d_in[8];
    const float* skw  = (const float*)d_in[9];
    const float* skb  = (const float*)d_in[10];
    const float* ow   = (const float*)d_in[11];
    const float* ob   = (const float*)d_in[12];
    float* out        = (float*)d_out;

    int N = in_sizes[0];

    convert_weights<<<(26 * 16384 + 255) / 256, 256>>>(in_w, w1, w2, skw, b2, skb);

    cudaFuncSetAttribute(pinn_mma, cudaFuncAttributeMaxDynamicSharedMemorySize, SMEM_BYTES);
    int grid = (N + MT - 1) / MT;
    pinn_mma<<<grid, THREADS, SMEM_BYTES>>>(S, T, B, in_b, b1, ow, ob, out, N);
}

// round 16
// speedup vs baseline: 1.2399x; 1.2399x over previous
#include <cuda_runtime.h>
#include <cuda_bf16.h>
#include <stdint.h>
#include <math.h>

typedef uint32_t u32;
typedef uint64_t u64;

static constexpr int THREADS = 256;
static constexpr int MT      = 128;     // points per CTA
static constexpr float OMEGA = 30.0f;
static constexpr int NSUB    = 52;      // 26 units x (hi,lo) 32KB subunits
static constexpr int SUB_BYTES = 32768;

// ---- shared memory layout (bytes) ----
static constexpr int RING_OFF  = 0;            // 3 x 32KB weight ring
static constexpr int FFRAG_OFF = 98304;        // ff fragments: 8 warps x 16KB = 128KB
static constexpr int BOW_OFF   = 229376;       // B (256 f) + out_w (128 f)
static constexpr int MBAR_OFF  = 230912;       // full[3] + cnt[3]
static constexpr int SMEM_BYTES = 231424;

// weight blob: 52 subunits x 32KB, execution order, bf16 [n][k] swizzled
__device__ __align__(16) unsigned char g_wblob[(size_t)NSUB * SUB_BYTES];
// precombined bias for epilogue2: b2[l] (+ skb[l/2] on even l)
__device__ __align__(16) float g_b2c[8 * 128];

// ============================ PTX helpers ============================

__device__ __forceinline__ u32 smem_u32(const void* p) {
    return (u32)__cvta_generic_to_shared(p);
}

#define MBARRIER_INIT(addr, cnt) \
    asm volatile("mbarrier.init.shared.b64 [%0], %1;" :: "r"(addr), "r"((u32)(cnt)) : "memory")
#define MBARRIER_EXPECT_TX(addr, b) \
    asm volatile("mbarrier.arrive.expect_tx.shared.b64 _, [%0], %1;" :: "r"(addr), "r"((u32)(b)) : "memory")

#define MBARRIER_WAIT_PARITY(mbar_smem_addr, phase_parity) do { \
    u32 _mbar = (u32)(mbar_smem_addr); \
    u32 _parity = (u32)(phase_parity); \
    u32 _done; \
    asm volatile( \
        "{\n\t.reg .pred p;\n\t" \
        "mbarrier.try_wait.parity.acquire.cta.shared::cta.b64 p, [%1], %2;\n\t" \
        "selp.b32 %0, 1, 0, p;\n\t}" \
        : "=r"(_done) : "r"(_mbar), "r"(_parity) : "memory"); \
    if (!_done) { \
        asm volatile( \
            "{\n\t.reg .pred P1;\n\t" \
            "WAIT_LOOP_%=:\n\t" \
            "mbarrier.try_wait.parity.acquire.cta.shared::cta.b64 P1, [%0], %1, 0x989680;\n\t" \
            "@P1 bra.uni WAIT_DONE_%=;\n\t" \
            "bra.uni WAIT_LOOP_%=;\n\t" \
            "WAIT_DONE_%=:\n\t}" \
            :: "r"(_mbar), "r"(_parity) : "memory"); \
    } \
} while (0)

__device__ __forceinline__ void bulk_copy(u32 dst, const void* src, u32 bytes, u32 mbar) {
    asm volatile(
        "cp.async.bulk.shared::cluster.global.mbarrier::complete_tx::bytes [%0], [%1], %2, [%3];"
        :: "r"(dst), "l"(src), "r"(bytes), "r"(mbar) : "memory");
}

__device__ __forceinline__ void ldsm4(u32& r0, u32& r1, u32& r2, u32& r3, u32 addr) {
    asm volatile("ldmatrix.sync.aligned.m8n8.x4.shared.b16 {%0,%1,%2,%3}, [%4];"
                 : "=r"(r0), "=r"(r1), "=r"(r2), "=r"(r3) : "r"(addr));
}

__device__ __forceinline__ void mma16816(float (&d)[4], const u32 (&a)[4], u32 b0, u32 b1) {
    asm volatile(
        "mma.sync.aligned.m16n8k16.row.col.f32.bf16.bf16.f32 "
        "{%0,%1,%2,%3},{%4,%5,%6,%7},{%8,%9},{%0,%1,%2,%3};"
        : "+f"(d[0]), "+f"(d[1]), "+f"(d[2]), "+f"(d[3])
        : "r"(a[0]), "r"(a[1]), "r"(a[2]), "r"(a[3]), "r"(b0), "r"(b1));
}

// first-MMA form: c = 0, writes d without needing prior zero-init
__device__ __forceinline__ void mma16816_z(float (&d)[4], const u32 (&a)[4], u32 b0, u32 b1) {
    float z = 0.0f;
    asm volatile(
        "mma.sync.aligned.m16n8k16.row.col.f32.bf16.bf16.f32 "
        "{%0,%1,%2,%3},{%4,%5,%6,%7},{%8,%9},{%10,%10,%10,%10};"
        : "=f"(d[0]), "=f"(d[1]), "=f"(d[2]), "=f"(d[3])
        : "r"(a[0]), "r"(a[1]), "r"(a[2]), "r"(a[3]), "r"(b0), "r"(b1), "f"(z));
}

// bf16 -> f32 is exactly bits<<16 (cheap ALU, no CVT)
__device__ __forceinline__ float bflo(u32 v) {
    return __uint_as_float(v << 16);
}
__device__ __forceinline__ float bfhi(u32 v) {
    return __uint_as_float(v & 0xFFFF0000u);
}

// split v0,v1 into packed bf16 hi + packed bf16 lo (residual), 1 CVT each way
__device__ __forceinline__ void bf_split2(float v0, float v1, u32& hi, u32& lo) {
    asm("cvt.rn.bf16x2.f32 %0, %1, %2;" : "=r"(hi) : "f"(v1), "f"(v0));
    float r0 = v0 - bflo(hi);
    float r1 = v1 - bfhi(hi);
    asm("cvt.rn.bf16x2.f32 %0, %1, %2;" : "=r"(lo) : "f"(r1), "f"(r0));
}

// ---- fast transcendentals (err ~1e-6, far below bf16-split noise) ----
__device__ __forceinline__ float fast_sin(float x) {
    float k = rintf(x * 0.15915494309189535f);
    float r = fmaf(k, -6.28125f, x);            // 6.28125 exact in fp32
    r = fmaf(k, -1.9353071795864769e-3f, r);    // 2*pi = 6.28125 + this
    float s;
    asm("sin.approx.f32 %0, %1;" : "=f"(s) : "f"(r));
    return s;
}
__device__ __forceinline__ float fast_cos(float x) {
    float k = rintf(x * 0.15915494309189535f);
    float r = fmaf(k, -6.28125f, x);
    r = fmaf(k, -1.9353071795864769e-3f, r);
    float c;
    asm("cos.approx.f32 %0, %1;" : "=f"(c) : "f"(r));
    return c;
}
__device__ __forceinline__ float fast_tanh(float x) {
    float e;
    asm("ex2.approx.f32 %0, %1;" : "=f"(e) : "f"(x * 2.8853900817779268f)); // exp(2x)
    float r;
    asm("rcp.approx.f32 %0, %1;" : "=f"(r) : "f"(e + 1.0f));
    return fmaf(-2.0f, r, 1.0f);   // 1 - 2/(e^{2x}+1)
}

// ==================== weight conversion pre-kernel ====================
// Unit order: in_w k0-127, in_w k128-255, then per layer l: w1_l, w2_l,
// (+ skw[l/2] k-chunk0, chunk1 when l even). Element (n,k) = W[k][n].
// In-tile layout: row n = 256B (128 bf16 of k), byte = n*256 + (2k ^ ((n&7)<<4)).
// Also fills g_b2c[l][c] = b2[l][c] + (l even ? skb[l/2][c] : 0).
__global__ void convert_weights(const float* __restrict__ in_w,
                                const float* __restrict__ w1,
                                const float* __restrict__ w2,
                                const float* __restrict__ skw,
                                const float* __restrict__ b2,
                                const float* __restrict__ skb) {
    int gid = blockIdx.x * blockDim.x + threadIdx.x;
    if (gid >= 26 * 16384) return;

    if (gid < 8 * 128) {
        int l = gid >> 7, c = gid & 127;
        float v = b2[l * 128 + c];
        if ((l & 1) == 0) v += skb[(l >> 1) * 128 + c];
        g_b2c[gid] = v;
    }

    int u = gid >> 14, e = gid & 16383;
    int n = e >> 7, k = e & 127;

    float v;
    if (u < 2) {
        v = in_w[(k + u * 128) * 128 + n];
    } else {
        int r = u - 2, l = 0;
        while (true) {
            int len = ((l & 1) == 0) ? 4 : 2;
            if (r < len) break;
            r -= len; l++;
        }
        if (r == 0)      v = w1[l * 16384 + k * 128 + n];
        else if (r == 1) v = w2[l * 16384 + k * 128 + n];
        else             v = skw[(l >> 1) * 32768 + (k + (r - 2) * 128) * 128 + n];
    }

    __nv_bfloat16 hi = __float2bfloat16_rn(v);
    float rem = v - __bfloat162float(hi);
    __nv_bfloat16 lo = __float2bfloat16_rn(rem);

    u32 off = (u32)(n * 256 + ((2 * k) ^ ((n & 7) << 4)));
    size_t base = (size_t)u * 65536;
    *(__nv_bfloat16*)(g_wblob + base + off)         = hi;
    *(__nv_bfloat16*)(g_wblob + base + 32768 + off) = lo;
}

// ==================== GEMM subunit helpers ====================
// Warp tile: m16 x n128 (16 ntiles). A row-major m16k16 frags, B = Wt[n][k]
// (col-major K x N), loaded via ldmatrix.x4 (2 ntiles x 1 kstep per ldsm).
// FIRST: this sub starts the accumulation group -> s==0 ah-MMAs use c=0 form
// (removes the 64-MOV zero-init and its WAR dependency).

template<bool FIRST>
__device__ __forceinline__ void gemm_x(u32 wbase, const u32 (&ah)[8][4], const u32 (&al)[8][4],
                                       bool isHi, float (&d)[16][4], int lane) {
    const u32 off0 = (u32)((((lane & 7) + ((lane >> 4) << 3))) * 256);
    const u32 swz  = (u32)((lane & 7) << 4);
    const u32 kh   = (u32)(((lane >> 3) & 1) * 16);
#pragma unroll
    for (int s = 0; s < 8; s++) {
#pragma unroll
        for (int ntp = 0; ntp < 8; ntp++) {
            u32 r0, r1, r2, r3;
            ldsm4(r0, r1, r2, r3, wbase + off0 + (u32)(ntp * 4096) + (((u32)(32 * s) + kh) ^ swz));
            if (FIRST && s == 0) {
                mma16816_z(d[2 * ntp],     ah[s], r0, r1);
                mma16816_z(d[2 * ntp + 1], ah[s], r2, r3);
            } else {
                mma16816(d[2 * ntp],     ah[s], r0, r1);
                mma16816(d[2 * ntp + 1], ah[s], r2, r3);
            }
            if (isHi) {
                mma16816(d[2 * ntp],     al[s], r0, r1);
                mma16816(d[2 * ntp + 1], al[s], r2, r3);
            }
        }
    }
}

template<bool FIRST>
__device__ __forceinline__ void gemm_ff(u32 wbase, const char* fr, int kbase,
                                        bool isHi, float (&d)[16][4], int lane) {
    const u32 off0 = (u32)((((lane & 7) + ((lane >> 4) << 3))) * 256);
    const u32 swz  = (u32)((lane & 7) << 4);
    const u32 kh   = (u32)(((lane >> 3) & 1) * 16);
#pragma unroll
    for (int s = 0; s < 8; s++) {
        const int4 q0 = *(const int4*)(fr + ((kbase + s) * 2 + 0) * 512);
        const int4 q1 = *(const int4*)(fr + ((kbase + s) * 2 + 1) * 512);
        u32 ah[4] = {(u32)q0.x, (u32)q1.x, (u32)q0.y, (u32)q1.y};
        u32 al[4] = {(u32)q0.z, (u32)q1.z, (u32)q0.w, (u32)q1.w};
#pragma unroll
        for (int ntp = 0; ntp < 8; ntp++) {
            u32 r0, r1, r2, r3;
            ldsm4(r0, r1, r2, r3, wbase + off0 + (u32)(ntp * 4096) + (((u32)(32 * s) + kh) ^ swz));
            if (FIRST && s == 0) {
                mma16816_z(d[2 * ntp],     ah, r0, r1);
                mma16816_z(d[2 * ntp + 1], ah, r2, r3);
            } else {
                mma16816(d[2 * ntp],     ah, r0, r1);
                mma16816(d[2 * ntp + 1], ah, r2, r3);
            }
            if (isHi) {
                mma16816(d[2 * ntp],     al, r0, r1);
                mma16816(d[2 * ntp + 1], al, r2, r3);
            }
        }
    }
}

__device__ __forceinline__ void prefetch_sub(u32 ring, u32 mbf, int sub) {
    u32 mb = mbf + 8 * (sub % 3);
    MBARRIER_EXPECT_TX(mb, SUB_BYTES);
    bulk_copy(ring + (sub % 3) * SUB_BYTES, g_wblob + (size_t)sub * SUB_BYTES, SUB_BYTES, mb);
}

// ==================== main kernel ====================

extern __shared__ __align__(16) char smem[];

__global__ void __launch_bounds__(THREADS, 1)
pinn_mma(const float* __restrict__ S,  const float* __restrict__ Tt,
         const float* __restrict__ Bm,
         const float* __restrict__ in_b, const float* __restrict__ b1,
         const float* __restrict__ ow,   const float* __restrict__ ob,
         float* __restrict__ out, int N)
{
    const int tid  = threadIdx.x;
    const int warp = tid >> 5, lane = tid & 31;
    const int grp  = lane >> 2, qc = lane & 3;
    const int base = blockIdx.x * MT;

    const u32 sb   = smem_u32(smem);
    const u32 ring = sb + RING_OFF;
    const u32 mbf  = sb + MBAR_OFF;        // full[3] at +0,8,16
    u32* cnt = (u32*)(smem + MBAR_OFF + 24);    // last-arriver counters [3]
    float* Bs  = (float*)(smem + BOW_OFF);      // 256 floats
    float* ows = Bs + 256;                      // 128 floats
    char*  fr  = smem + FFRAG_OFF + warp * 16384 + lane * 16;  // this thread's frag base

    if (tid == 0) {
        MBARRIER_INIT(mbf + 0,  1);
        MBARRIER_INIT(mbf + 8,  1);
        MBARRIER_INIT(mbf + 16, 1);
        cnt[0] = 0; cnt[1] = 0; cnt[2] = 0;
    }
    __syncthreads();   // barrier/counter init visible before any wait/arrive below

    if (tid == 0) {
        prefetch_sub(ring, mbf, 0);
        prefetch_sub(ring, mbf, 1);
        prefetch_sub(ring, mbf, 2);
    }

    // stage B and out_w
    if (tid < 256) Bs[tid] = Bm[tid];
    if (tid < 128) ows[tid] = ow[tid];

    // this thread's two point rows
    const int r0g = base + warp * 16 + grp;
    const int r1g = r0g + 8;
    const float s0 = (r0g < N) ? S[r0g]  : 0.0f;
    const float t0 = (r0g < N) ? Tt[r0g] : 0.0f;
    const float s1 = (r1g < N) ? S[r1g]  : 0.0f;
    const float t1 = (r1g < N) ? Tt[r1g] : 0.0f;
    __syncthreads();

    // ---- Fourier-feature A fragments -> per-warp smem (overlaps weight copies) ----
    // A[m][k]: k<128 sin(proj[f=k]); k>=128 cos(proj[f=k-128]).
    // kstep t (sin) / t+8 (cos); within kstep, this thread needs f = 16t + {2qc,2qc+1,2qc+8,2qc+9}.
#pragma unroll
    for (int t = 0; t < 8; t++) {
        int f0 = 16 * t + 2 * qc;
        float sn[2][4], cs[2][4];
#pragma unroll
        for (int j = 0; j < 4; j++) {
            int f = f0 + ((j & 1) ? 1 : 0) + ((j & 2) ? 8 : 0);
            float p0 = s0 * Bs[f] + t0 * Bs[128 + f];
            float p1 = s1 * Bs[f] + t1 * Bs[128 + f];
            sn[0][j] = fast_sin(p0);  cs[0][j] = fast_cos(p0);
            sn[1][j] = fast_sin(p1);  cs[1][j] = fast_cos(p1);
        }
        u32 h0, l0, h1, l1, h2, l2, h3, l3;
        // sin -> kstep t
        bf_split2(sn[0][0], sn[0][1], h0, l0);   // a0: row grp,  f0,f0+1
        bf_split2(sn[1][0], sn[1][1], h1, l1);   // a1: row grp+8
        bf_split2(sn[0][2], sn[0][3], h2, l2);   // a2: row grp,  f0+8,f0+9
        bf_split2(sn[1][2], sn[1][3], h3, l3);   // a3
        *(int4*)(fr + (t * 2 + 0) * 512) = make_int4((int)h0, (int)h2, (int)l0, (int)l2);
        *(int4*)(fr + (t * 2 + 1) * 512) = make_int4((int)h1, (int)h3, (int)l1, (int)l3);
        // cos -> kstep t+8
        bf_split2(cs[0][0], cs[0][1], h0, l0);
        bf_split2(cs[1][0], cs[1][1], h1, l1);
        bf_split2(cs[0][2], cs[0][3], h2, l2);
        bf_split2(cs[1][2], cs[1][3], h3, l3);
        *(int4*)(fr + ((t + 8) * 2 + 0) * 512) = make_int4((int)h0, (int)h2, (int)l0, (int)l2);
        *(int4*)(fr + ((t + 8) * 2 + 1) * 512) = make_int4((int)h1, (int)h3, (int)l1, (int)l3);
    }
    // (no sync needed: each thread reads back only its own records)

    // ---- phase stagger: delay warps 4-7 (~epilogue length) so each SMSP's two
    // warps run anti-phase. With last-arriver refill, NO warp blocks on empty,
    // so warp 0 keeps its lead and every SMSP gets a true early/late pair. ----
    if (warp >= 4) {
        u32 c0; asm volatile("mov.u32 %0, %%clock;" : "=r"(c0));
        u32 el = 0;
        do { u32 c; asm volatile("mov.u32 %0, %%clock;" : "=r"(c)); el = c - c0; } while (el < 2600u);
    }

    int sub = 0;
    float d[16][4];
    u32 xh[8][4], xl[8][4];

    // Per-sub protocol (no CTA barriers, no blocking producer):
    //  - each warp: wait full(sub) [acquire], gemm, lane0 atomicAdd on cnt[slot]
    //  - the 8th (last) arriver for this use issues the refill of sub+3.
#define DO_SUB(GEMM_CALL) do { \
        MBARRIER_WAIT_PARITY(mbf + 8 * (sub % 3), (sub / 3) & 1); \
        GEMM_CALL; \
        if (lane == 0) { \
            u32 old = atomicAdd(&cnt[sub % 3], 1u); \
            if (old == 8u * (u32)(sub / 3) + 7u && sub + 3 < NSUB) \
                prefetch_sub(ring, mbf, sub + 3); \
        } \
        sub++; \
    } while (0)

#define DO_FF(kbase, isHi, FIRST) \
    DO_SUB((gemm_ff<FIRST>(ring + (u32)((sub % 3) * SUB_BYTES), fr, (kbase), (isHi), d, lane)))
#define DO_X(AH, AL, isHi, FIRST) \
    DO_SUB((gemm_x<FIRST>(ring + (u32)((sub % 3) * SUB_BYTES), (AH), (AL), (isHi), d, lane)))

    // ---- input layer: D = ff @ in_w (K=256), x = sin(OMEGA*(D + in_b)) ----
    DO_FF(0, true, true);   DO_FF(0, false, false);
    DO_FF(8, true, false);  DO_FF(8, false, false);

#pragma unroll
    for (int s = 0; s < 8; s++) {
#pragma unroll
        for (int p = 0; p < 2; p++) {
            int nt = 2 * s + p;
            int col = 8 * nt + 2 * qc;
            float2 bb = *(const float2*)(in_b + col);
            float v00 = fast_sin(OMEGA * (d[nt][0] + bb.x));
            float v01 = fast_sin(OMEGA * (d[nt][1] + bb.y));
            float v10 = fast_sin(OMEGA * (d[nt][2] + bb.x));
            float v11 = fast_sin(OMEGA * (d[nt][3] + bb.y));
            bf_split2(v00, v01, xh[s][2 * p],     xl[s][2 * p]);
            bf_split2(v10, v11, xh[s][2 * p + 1], xl[s][2 * p + 1]);
        }
    }

    // ---- residual blocks ----
    for (int l = 0; l < 8; l++) {
        const bool skip = ((l & 1) == 0);
        u32 hh[8][4], hl[8][4];

        // GEMM1: D = x @ w1_l ; h = tanh(D + b1_l)
        DO_X(xh, xl, true, true);  DO_X(xh, xl, false, false);
#pragma unroll
        for (int s = 0; s < 8; s++) {
#pragma unroll
            for (int p = 0; p < 2; p++) {
                int nt = 2 * s + p;
                int col = 8 * nt + 2 * qc;
                float2 bb = *(const float2*)(b1 + l * 128 + col);
                float v00 = fast_tanh(d[nt][0] + bb.x);
                float v01 = fast_tanh(d[nt][1] + bb.y);
                float v10 = fast_tanh(d[nt][2] + bb.x);
                float v11 = fast_tanh(d[nt][3] + bb.y);
                bf_split2(v00, v01, hh[s][2 * p],     hl[s][2 * p]);
                bf_split2(v10, v11, hh[s][2 * p + 1], hl[s][2 * p + 1]);
            }
        }

        // GEMM2: D = h @ w2_l (+ ff @ skip_w[l/2])
        DO_X(hh, hl, true, true);  DO_X(hh, hl, false, false);
        if (skip) {
            DO_FF(0, true, false);  DO_FF(0, false, false);
            DO_FF(8, true, false);  DO_FF(8, false, false);
        }

        // epilogue2: x = x + D + b2c (precombined b2 + skb); re-split into frags
#pragma unroll
        for (int s = 0; s < 8; s++) {
#pragma unroll
            for (int p = 0; p < 2; p++) {
                int nt = 2 * s + p;
                int col = 8 * nt + 2 * qc;
                float2 bb = *(const float2*)(g_b2c + l * 128 + col);
                int i0 = 2 * p, i1 = 2 * p + 1;
                float v00 = bflo(xh[s][i0]) + bflo(xl[s][i0]) + d[nt][0] + bb.x;
                float v01 = bfhi(xh[s][i0]) + bfhi(xl[s][i0]) + d[nt][1] + bb.y;
                float v10 = bflo(xh[s][i1]) + bflo(xl[s][i1]) + d[nt][2] + bb.x;
                float v11 = bfhi(xh[s][i1]) + bfhi(xl[s][i1]) + d[nt][3] + bb.y;
                bf_split2(v00, v01, xh[s][i0], xl[s][i0]);
                bf_split2(v10, v11, xh[s][i1], xl[s][i1]);
            }
        }
    }

    // ---- output layer: out = x @ out_w + out_b ----
    float a0 = 0.0f, a1 = 0.0f;
#pragma unroll
    for (int s = 0; s < 8; s++) {
#pragma unroll
        for (int p = 0; p < 2; p++) {
            int nt = 2 * s + p;
            int col = 8 * nt + 2 * qc;
            float w0 = ows[col], w1v = ows[col + 1];
            int i0 = 2 * p, i1 = 2 * p + 1;
            a0 += (bflo(xh[s][i0]) + bflo(xl[s][i0])) * w0
                + (bfhi(xh[s][i0]) + bfhi(xl[s][i0])) * w1v;
            a1 += (bflo(xh[s][i1]) + bflo(xl[s][i1])) * w0
                + (bfhi(xh[s][i1]) + bfhi(xl[s][i1])) * w1v;
        }
    }
    a0 += __shfl_xor_sync(0xFFFFFFFF, a0, 1);
    a0 += __shfl_xor_sync(0xFFFFFFFF, a0, 2);
    a1 += __shfl_xor_sync(0xFFFFFFFF, a1, 1);
    a1 += __shfl_xor_sync(0xFFFFFFFF, a1, 2);
    if (qc == 0) {
        float obv = ob[0];
        if (r0g < N) out[r0g] = a0 + obv;
        if (r1g < N) out[r1g] = a1 + obv;
    }
#undef DO_FF
#undef DO_X
#undef DO_SUB
}

// ==================== launcher ====================

extern "C" void kernel_launch(void* const* d_in, const int* in_sizes, int n_in,
                              void* d_out, int out_size) {
    const float* S    = (const float*)d_in[0];
    const float* T    = (const float*)d_in[1];
    const float* B    = (const float*)d_in[2];
    const float* in_w = (const float*)d_in[3];
    const float* in_b = (const float*)d_in[4];
    const float* w1   = (const float*)d_in[5];
    const float* b1   = (const float*)d_in[6];
    const float* w2   = (const float*)d_in[7];
    const float* b2   = (const float*)d_in[8];
    const float* skw  = (const float*)d_in[9];
    const float* skb  = (const float*)d_in[10];
    const float* ow   = (const float*)d_in[11];
    const float* ob   = (const float*)d_in[12];
    float* out        = (float*)d_out;

    int N = in_sizes[0];

    convert_weights<<<(26 * 16384 + 255) / 256, 256>>>(in_w, w1, w2, skw, b2, skb);

    cudaFuncSetAttribute(pinn_mma, cudaFuncAttributeMaxDynamicSharedMemorySize, SMEM_BYTES);
    int grid = (N + MT - 1) / MT;
    pinn_mma<<<grid, THREADS, SMEM_BYTES>>>(S, T, B, in_b, b1, ow, ob, out, N);
}

// round 17
// speedup vs baseline: 1.2404x; 1.0004x over previous
#include <cuda_runtime.h>
#include <cuda_bf16.h>
#include <stdint.h>
#include <math.h>

typedef uint32_t u32;
typedef uint64_t u64;

static constexpr int THREADS = 256;
static constexpr int MT      = 128;     // points per tile
static constexpr float OMEGA = 30.0f;
static constexpr int NSUB    = 52;      // subs per tile (26 units x hi/lo)
static constexpr int SUB_BYTES = 32768;
static constexpr int GRID    = 148;     // persistent: 1 CTA per SM

// ---- shared memory layout (bytes) ----
static constexpr int RING_OFF  = 0;            // 3 x 32KB weight ring
static constexpr int FFRAG_OFF = 98304;        // ff fragments: 8 warps x 16KB
static constexpr int BOW_OFF   = 229376;       // B (256 f) + out_w (128 f)
static constexpr int MBAR_OFF  = 230912;       // full[3] + cnt[3]
static constexpr int SMEM_BYTES = 231424;

__device__ __align__(16) unsigned char g_wblob[(size_t)NSUB * SUB_BYTES];
__device__ __align__(16) float g_b2c[8 * 128];

// ============================ PTX helpers ============================

__device__ __forceinline__ u32 smem_u32(const void* p) {
    return (u32)__cvta_generic_to_shared(p);
}

#define MBARRIER_INIT(addr, cnt) \
    asm volatile("mbarrier.init.shared.b64 [%0], %1;" :: "r"(addr), "r"((u32)(cnt)) : "memory")
#define MBARRIER_EXPECT_TX(addr, b) \
    asm volatile("mbarrier.arrive.expect_tx.shared.b64 _, [%0], %1;" :: "r"(addr), "r"((u32)(b)) : "memory")

#define MBARRIER_WAIT_PARITY(mbar_smem_addr, phase_parity) do { \
    u32 _mbar = (u32)(mbar_smem_addr); \
    u32 _parity = (u32)(phase_parity); \
    u32 _done; \
    asm volatile( \
        "{\n\t.reg .pred p;\n\t" \
        "mbarrier.try_wait.parity.acquire.cta.shared::cta.b64 p, [%1], %2;\n\t" \
        "selp.b32 %0, 1, 0, p;\n\t}" \
        : "=r"(_done) : "r"(_mbar), "r"(_parity) : "memory"); \
    if (!_done) { \
        asm volatile( \
            "{\n\t.reg .pred P1;\n\t" \
            "WAIT_LOOP_%=:\n\t" \
            "mbarrier.try_wait.parity.acquire.cta.shared::cta.b64 P1, [%0], %1, 0x989680;\n\t" \
            "@P1 bra.uni WAIT_DONE_%=;\n\t" \
            "bra.uni WAIT_LOOP_%=;\n\t" \
            "WAIT_DONE_%=:\n\t}" \
            :: "r"(_mbar), "r"(_parity) : "memory"); \
    } \
} while (0)

__device__ __forceinline__ void bulk_copy(u32 dst, const void* src, u32 bytes, u32 mbar) {
    asm volatile(
        "cp.async.bulk.shared::cluster.global.mbarrier::complete_tx::bytes [%0], [%1], %2, [%3];"
        :: "r"(dst), "l"(src), "r"(bytes), "r"(mbar) : "memory");
}

__device__ __forceinline__ void ldsm4(u32& r0, u32& r1, u32& r2, u32& r3, u32 addr) {
    asm volatile("ldmatrix.sync.aligned.m8n8.x4.shared.b16 {%0,%1,%2,%3}, [%4];"
                 : "=r"(r0), "=r"(r1), "=r"(r2), "=r"(r3) : "r"(addr));
}

__device__ __forceinline__ void mma16816(float (&d)[4], const u32 (&a)[4], u32 b0, u32 b1) {
    asm volatile(
        "mma.sync.aligned.m16n8k16.row.col.f32.bf16.bf16.f32 "
        "{%0,%1,%2,%3},{%4,%5,%6,%7},{%8,%9},{%0,%1,%2,%3};"
        : "+f"(d[0]), "+f"(d[1]), "+f"(d[2]), "+f"(d[3])
        : "r"(a[0]), "r"(a[1]), "r"(a[2]), "r"(a[3]), "r"(b0), "r"(b1));
}

// first-MMA form: c = 0 (no prior zero-init needed)
__device__ __forceinline__ void mma16816_z(float (&d)[4], const u32 (&a)[4], u32 b0, u32 b1) {
    float z = 0.0f;
    asm volatile(
        "mma.sync.aligned.m16n8k16.row.col.f32.bf16.bf16.f32 "
        "{%0,%1,%2,%3},{%4,%5,%6,%7},{%8,%9},{%10,%10,%10,%10};"
        : "=f"(d[0]), "=f"(d[1]), "=f"(d[2]), "=f"(d[3])
        : "r"(a[0]), "r"(a[1]), "r"(a[2]), "r"(a[3]), "r"(b0), "r"(b1), "f"(z));
}

__device__ __forceinline__ float bflo(u32 v) { return __uint_as_float(v << 16); }
__device__ __forceinline__ float bfhi(u32 v) { return __uint_as_float(v & 0xFFFF0000u); }

__device__ __forceinline__ void bf_split2(float v0, float v1, u32& hi, u32& lo) {
    asm("cvt.rn.bf16x2.f32 %0, %1, %2;" : "=r"(hi) : "f"(v1), "f"(v0));
    float r0 = v0 - bflo(hi);
    float r1 = v1 - bfhi(hi);
    asm("cvt.rn.bf16x2.f32 %0, %1, %2;" : "=r"(lo) : "f"(r1), "f"(r0));
}

// ---- fast transcendentals (err ~1e-6) ----
__device__ __forceinline__ float fast_sin(float x) {
    float k = rintf(x * 0.15915494309189535f);
    float r = fmaf(k, -6.28125f, x);
    r = fmaf(k, -1.9353071795864769e-3f, r);
    float s;
    asm("sin.approx.f32 %0, %1;" : "=f"(s) : "f"(r));
    return s;
}
__device__ __forceinline__ float fast_cos(float x) {
    float k = rintf(x * 0.15915494309189535f);
    float r = fmaf(k, -6.28125f, x);
    r = fmaf(k, -1.9353071795864769e-3f, r);
    float c;
    asm("cos.approx.f32 %0, %1;" : "=f"(c) : "f"(r));
    return c;
}
__device__ __forceinline__ float fast_tanh(float x) {
    float e;
    asm("ex2.approx.f32 %0, %1;" : "=f"(e) : "f"(x * 2.8853900817779268f));
    float r;
    asm("rcp.approx.f32 %0, %1;" : "=f"(r) : "f"(e + 1.0f));
    return fmaf(-2.0f, r, 1.0f);
}

// ==================== weight conversion pre-kernel (unchanged) ====================
__global__ void convert_weights(const float* __restrict__ in_w,
                                const float* __restrict__ w1,
                                const float* __restrict__ w2,
                                const float* __restrict__ skw,
                                const float* __restrict__ b2,
                                const float* __restrict__ skb) {
    int gid = blockIdx.x * blockDim.x + threadIdx.x;
    if (gid >= 26 * 16384) return;

    if (gid < 8 * 128) {
        int l = gid >> 7, c = gid & 127;
        float v = b2[l * 128 + c];
        if ((l & 1) == 0) v += skb[(l >> 1) * 128 + c];
        g_b2c[gid] = v;
    }

    int u = gid >> 14, e = gid & 16383;
    int n = e >> 7, k = e & 127;

    float v;
    if (u < 2) {
        v = in_w[(k + u * 128) * 128 + n];
    } else {
        int r = u - 2, l = 0;
        while (true) {
            int len = ((l & 1) == 0) ? 4 : 2;
            if (r < len) break;
            r -= len; l++;
        }
        if (r == 0)      v = w1[l * 16384 + k * 128 + n];
        else if (r == 1) v = w2[l * 16384 + k * 128 + n];
        else             v = skw[(l >> 1) * 32768 + (k + (r - 2) * 128) * 128 + n];
    }

    __nv_bfloat16 hi = __float2bfloat16_rn(v);
    float rem = v - __bfloat162float(hi);
    __nv_bfloat16 lo = __float2bfloat16_rn(rem);

    u32 off = (u32)(n * 256 + ((2 * k) ^ ((n & 7) << 4)));
    size_t base = (size_t)u * 65536;
    *(__nv_bfloat16*)(g_wblob + base + off)         = hi;
    *(__nv_bfloat16*)(g_wblob + base + 32768 + off) = lo;
}

// ==================== GEMM subunit helpers (unchanged structure) ====================

template<bool FIRST>
__device__ __forceinline__ void gemm_x(u32 wbase, const u32 (&ah)[8][4], const u32 (&al)[8][4],
                                       bool isHi, float (&d)[16][4], int lane) {
    const u32 off0 = (u32)((((lane & 7) + ((lane >> 4) << 3))) * 256);
    const u32 swz  = (u32)((lane & 7) << 4);
    const u32 kh   = (u32)(((lane >> 3) & 1) * 16);
#pragma unroll
    for (int s = 0; s < 8; s++) {
#pragma unroll
        for (int ntp = 0; ntp < 8; ntp++) {
            u32 r0, r1, r2, r3;
            ldsm4(r0, r1, r2, r3, wbase + off0 + (u32)(ntp * 4096) + (((u32)(32 * s) + kh) ^ swz));
            if (FIRST && s == 0) {
                mma16816_z(d[2 * ntp],     ah[s], r0, r1);
                mma16816_z(d[2 * ntp + 1], ah[s], r2, r3);
            } else {
                mma16816(d[2 * ntp],     ah[s], r0, r1);
                mma16816(d[2 * ntp + 1], ah[s], r2, r3);
            }
            if (isHi) {
                mma16816(d[2 * ntp],     al[s], r0, r1);
                mma16816(d[2 * ntp + 1], al[s], r2, r3);
            }
        }
    }
}

template<bool FIRST>
__device__ __forceinline__ void gemm_ff(u32 wbase, const char* fr, int kbase,
                                        bool isHi, float (&d)[16][4], int lane) {
    const u32 off0 = (u32)((((lane & 7) + ((lane >> 4) << 3))) * 256);
    const u32 swz  = (u32)((lane & 7) << 4);
    const u32 kh   = (u32)(((lane >> 3) & 1) * 16);
#pragma unroll
    for (int s = 0; s < 8; s++) {
        const int4 q0 = *(const int4*)(fr + ((kbase + s) * 2 + 0) * 512);
        const int4 q1 = *(const int4*)(fr + ((kbase + s) * 2 + 1) * 512);
        u32 ah[4] = {(u32)q0.x, (u32)q1.x, (u32)q0.y, (u32)q1.y};
        u32 al[4] = {(u32)q0.z, (u32)q1.z, (u32)q0.w, (u32)q1.w};
#pragma unroll
        for (int ntp = 0; ntp < 8; ntp++) {
            u32 r0, r1, r2, r3;
            ldsm4(r0, r1, r2, r3, wbase + off0 + (u32)(ntp * 4096) + (((u32)(32 * s) + kh) ^ swz));
            if (FIRST && s == 0) {
                mma16816_z(d[2 * ntp],     ah, r0, r1);
                mma16816_z(d[2 * ntp + 1], ah, r2, r3);
            } else {
                mma16816(d[2 * ntp],     ah, r0, r1);
                mma16816(d[2 * ntp + 1], ah, r2, r3);
            }
            if (isHi) {
                mma16816(d[2 * ntp],     al, r0, r1);
                mma16816(d[2 * ntp + 1], al, r2, r3);
            }
        }
    }
}

// persistent-aware prefetch: slot/parity from GLOBAL sub index, weight unit = gsub % 52
__device__ __forceinline__ void prefetch_sub(u32 ring, u32 mbf, int gsub) {
    u32 mb = mbf + 8 * (gsub % 3);
    MBARRIER_EXPECT_TX(mb, SUB_BYTES);
    bulk_copy(ring + (gsub % 3) * SUB_BYTES, g_wblob + (size_t)(gsub % NSUB) * SUB_BYTES,
              SUB_BYTES, mb);
}

// ==================== main kernel (persistent CTAs) ====================

extern __shared__ __align__(16) char smem[];

__global__ void __launch_bounds__(THREADS, 1)
pinn_mma(const float* __restrict__ S,  const float* __restrict__ Tt,
         const float* __restrict__ Bm,
         const float* __restrict__ in_b, const float* __restrict__ b1,
         const float* __restrict__ ow,   const float* __restrict__ ob,
         float* __restrict__ out, int N, int ntiles)
{
    const int tid  = threadIdx.x;
    const int warp = tid >> 5, lane = tid & 31;
    const int grp  = lane >> 2, qc = lane & 3;

    const u32 sb   = smem_u32(smem);
    const u32 ring = sb + RING_OFF;
    const u32 mbf  = sb + MBAR_OFF;
    u32* cnt = (u32*)(smem + MBAR_OFF + 24);
    float* Bs  = (float*)(smem + BOW_OFF);
    float* ows = Bs + 256;
    char*  fr  = smem + FFRAG_OFF + warp * 16384 + lane * 16;

    // total subs this CTA will execute (52 per tile)
    const int my_tiles = (ntiles - (int)blockIdx.x + (int)gridDim.x - 1) / (int)gridDim.x;
    if (my_tiles <= 0) return;
    const int total_subs = my_tiles * NSUB;

    if (tid == 0) {
        MBARRIER_INIT(mbf + 0,  1);
        MBARRIER_INIT(mbf + 8,  1);
        MBARRIER_INIT(mbf + 16, 1);
        cnt[0] = 0; cnt[1] = 0; cnt[2] = 0;
    }
    __syncthreads();

    if (tid == 0) {
        prefetch_sub(ring, mbf, 0);
        prefetch_sub(ring, mbf, 1);
        prefetch_sub(ring, mbf, 2);
    }

    // one-time staging
    if (tid < 256) Bs[tid] = Bm[tid];
    if (tid < 128) ows[tid] = ow[tid];
    __syncthreads();

    // one-time phase stagger (persists across tiles since nothing re-syncs CTA-wide)
    if (warp >= 4) {
        u32 c0; asm volatile("mov.u32 %0, %%clock;" : "=r"(c0));
        u32 el = 0;
        do { u32 c; asm volatile("mov.u32 %0, %%clock;" : "=r"(c)); el = c - c0; } while (el < 2600u);
    }

    int sub = 0;                 // GLOBAL running sub counter (across tiles)
    float d[16][4];
    u32 xh[8][4], xl[8][4];

#define DO_SUB(GEMM_CALL) do { \
        MBARRIER_WAIT_PARITY(mbf + 8 * (sub % 3), (sub / 3) & 1); \
        GEMM_CALL; \
        if (lane == 0) { \
            u32 old = atomicAdd(&cnt[sub % 3], 1u); \
            if (old == 8u * (u32)(sub / 3) + 7u && sub + 3 < total_subs) \
                prefetch_sub(ring, mbf, sub + 3); \
        } \
        sub++; \
    } while (0)

#define DO_FF(kbase, isHi, FIRST) \
    DO_SUB((gemm_ff<FIRST>(ring + (u32)((sub % 3) * SUB_BYTES), fr, (kbase), (isHi), d, lane)))
#define DO_X(AH, AL, isHi, FIRST) \
    DO_SUB((gemm_x<FIRST>(ring + (u32)((sub % 3) * SUB_BYTES), (AH), (AL), (isHi), d, lane)))

    // ==================== persistent tile loop ====================
    for (int tile = blockIdx.x; tile < ntiles; tile += gridDim.x) {
        const int base = tile * MT;
        const int r0g = base + warp * 16 + grp;
        const int r1g = r0g + 8;
        const float s0 = (r0g < N) ? S[r0g]  : 0.0f;
        const float t0 = (r0g < N) ? Tt[r0g] : 0.0f;
        const float s1 = (r1g < N) ? S[r1g]  : 0.0f;
        const float t1 = (r1g < N) ? Tt[r1g] : 0.0f;

        // ---- Fourier-feature A fragments -> per-warp smem (warp-private) ----
#pragma unroll
        for (int t = 0; t < 8; t++) {
            int f0 = 16 * t + 2 * qc;
            float sn[2][4], cs[2][4];
#pragma unroll
            for (int j = 0; j < 4; j++) {
                int f = f0 + ((j & 1) ? 1 : 0) + ((j & 2) ? 8 : 0);
                float p0 = s0 * Bs[f] + t0 * Bs[128 + f];
                float p1 = s1 * Bs[f] + t1 * Bs[128 + f];
                sn[0][j] = fast_sin(p0);  cs[0][j] = fast_cos(p0);
                sn[1][j] = fast_sin(p1);  cs[1][j] = fast_cos(p1);
            }
            u32 h0, l0, h1, l1, h2, l2, h3, l3;
            bf_split2(sn[0][0], sn[0][1], h0, l0);
            bf_split2(sn[1][0], sn[1][1], h1, l1);
            bf_split2(sn[0][2], sn[0][3], h2, l2);
            bf_split2(sn[1][2], sn[1][3], h3, l3);
            *(int4*)(fr + (t * 2 + 0) * 512) = make_int4((int)h0, (int)h2, (int)l0, (int)l2);
            *(int4*)(fr + (t * 2 + 1) * 512) = make_int4((int)h1, (int)h3, (int)l1, (int)l3);
            bf_split2(cs[0][0], cs[0][1], h0, l0);
            bf_split2(cs[1][0], cs[1][1], h1, l1);
            bf_split2(cs[0][2], cs[0][3], h2, l2);
            bf_split2(cs[1][2], cs[1][3], h3, l3);
            *(int4*)(fr + ((t + 8) * 2 + 0) * 512) = make_int4((int)h0, (int)h2, (int)l0, (int)l2);
            *(int4*)(fr + ((t + 8) * 2 + 1) * 512) = make_int4((int)h1, (int)h3, (int)l1, (int)l3);
        }

        // ---- input layer: D = ff @ in_w (K=256), x = sin(OMEGA*(D + in_b)) ----
        DO_FF(0, true, true);   DO_FF(0, false, false);
        DO_FF(8, true, false);  DO_FF(8, false, false);

#pragma unroll
        for (int s = 0; s < 8; s++) {
#pragma unroll
            for (int p = 0; p < 2; p++) {
                int nt = 2 * s + p;
                int col = 8 * nt + 2 * qc;
                float2 bb = *(const float2*)(in_b + col);
                float v00 = fast_sin(OMEGA * (d[nt][0] + bb.x));
                float v01 = fast_sin(OMEGA * (d[nt][1] + bb.y));
                float v10 = fast_sin(OMEGA * (d[nt][2] + bb.x));
                float v11 = fast_sin(OMEGA * (d[nt][3] + bb.y));
                bf_split2(v00, v01, xh[s][2 * p],     xl[s][2 * p]);
                bf_split2(v10, v11, xh[s][2 * p + 1], xl[s][2 * p + 1]);
            }
        }

        // ---- residual blocks ----
        for (int l = 0; l < 8; l++) {
            const bool skip = ((l & 1) == 0);
            u32 hh[8][4], hl[8][4];

            // GEMM1: D = x @ w1_l ; h = tanh(D + b1_l)
            DO_X(xh, xl, true, true);  DO_X(xh, xl, false, false);
#pragma unroll
            for (int s = 0; s < 8; s++) {
#pragma unroll
                for (int p = 0; p < 2; p++) {
                    int nt = 2 * s + p;
                    int col = 8 * nt + 2 * qc;
                    float2 bb = *(const float2*)(b1 + l * 128 + col);
                    float v00 = fast_tanh(d[nt][0] + bb.x);
                    float v01 = fast_tanh(d[nt][1] + bb.y);
                    float v10 = fast_tanh(d[nt][2] + bb.x);
                    float v11 = fast_tanh(d[nt][3] + bb.y);
                    bf_split2(v00, v01, hh[s][2 * p],     hl[s][2 * p]);
                    bf_split2(v10, v11, hh[s][2 * p + 1], hl[s][2 * p + 1]);
                }
            }

            // GEMM2: D = h @ w2_l (+ ff @ skip_w[l/2])
            DO_X(hh, hl, true, true);  DO_X(hh, hl, false, false);
            if (skip) {
                DO_FF(0, true, false);  DO_FF(0, false, false);
                DO_FF(8, true, false);  DO_FF(8, false, false);
            }

            // epilogue2: x = x + D + b2c
#pragma unroll
            for (int s = 0; s < 8; s++) {
#pragma unroll
                for (int p = 0; p < 2; p++) {
                    int nt = 2 * s + p;
                    int col = 8 * nt + 2 * qc;
                    float2 bb = *(const float2*)(g_b2c + l * 128 + col);
                    int i0 = 2 * p, i1 = 2 * p + 1;
                    float v00 = bflo(xh[s][i0]) + bflo(xl[s][i0]) + d[nt][0] + bb.x;
                    float v01 = bfhi(xh[s][i0]) + bfhi(xl[s][i0]) + d[nt][1] + bb.y;
                    float v10 = bflo(xh[s][i1]) + bflo(xl[s][i1]) + d[nt][2] + bb.x;
                    float v11 = bfhi(xh[s][i1]) + bfhi(xl[s][i1]) + d[nt][3] + bb.y;
                    bf_split2(v00, v01, xh[s][i0], xl[s][i0]);
                    bf_split2(v10, v11, xh[s][i1], xl[s][i1]);
                }
            }
        }

        // ---- output layer: out = x @ out_w + out_b ----
        float a0 = 0.0f, a1 = 0.0f;
#pragma unroll
        for (int s = 0; s < 8; s++) {
#pragma unroll
            for (int p = 0; p < 2; p++) {
                int nt = 2 * s + p;
                int col = 8 * nt + 2 * qc;
                float w0 = ows[col], w1v = ows[col + 1];
                int i0 = 2 * p, i1 = 2 * p + 1;
                a0 += (bflo(xh[s][i0]) + bflo(xl[s][i0])) * w0
                    + (bfhi(xh[s][i0]) + bfhi(xl[s][i0])) * w1v;
                a1 += (bflo(xh[s][i1]) + bflo(xl[s][i1])) * w0
                    + (bfhi(xh[s][i1]) + bfhi(xl[s][i1])) * w1v;
            }
        }
        a0 += __shfl_xor_sync(0xFFFFFFFF, a0, 1);
        a0 += __shfl_xor_sync(0xFFFFFFFF, a0, 2);
        a1 += __shfl_xor_sync(0xFFFFFFFF, a1, 1);
        a1 += __shfl_xor_sync(0xFFFFFFFF, a1, 2);
        if (qc == 0) {
            float obv = ob[0];
            if (r0g < N) out[r0g] = a0 + obv;
            if (r1g < N) out[r1g] = a1 + obv;
        }
    }
#undef DO_FF
#undef DO_X
#undef DO_SUB
}

// ==================== launcher ====================

extern "C" void kernel_launch(void* const* d_in, const int* in_sizes, int n_in,
                              void* d_out, int out_size) {
    const float* S    = (const float*)d_in[0];
    const float* T    = (const float*)d_in[1];
    const float* B    = (const float*)d_in[2];
    const float* in_w = (const float*)d_in[3];
    const float* in_b = (const float*)d_in[4];
    const float* w1   = (const float*)d_in[5];
    const float* b1   = (const float*)d_in[6];
    const float* w2   = (const float*)d_in[7];
    const float* b2   = (const float*)d_in[8];
    const float* skw  = (const float*)d_in[9];
    const float* skb  = (const float*)d_in[10];
    const float* ow   = (const float*)d_in[11];
    const float* ob   = (const float*)d_in[12];
    float* out        = (float*)d_out;

    int N = in_sizes[0];
    int ntiles = (N + MT - 1) / MT;
    int grid = (ntiles < GRID) ? ntiles : GRID;

    convert_weights<<<(26 * 16384 + 255) / 256, 256>>>(in_w, w1, w2, skw, b2, skb);

    cudaFuncSetAttribute(pinn_mma, cudaFuncAttributeMaxDynamicSharedMemorySize, SMEM_BYTES);
    pinn_mma<<<grid, THREADS, SMEM_BYTES>>>(S, T, B, in_b, b1, ow, ob, out, N, ntiles);
}